// round 3
// baseline (speedup 1.0000x reference)
#include <cuda_runtime.h>
#include <cuda_fp16.h>

#define DI __device__ __forceinline__

// ---------------- problem constants ----------------
#define LL   3072
#define DD   1024
#define HH   16
#define HDM  64
#define SS   512
#define DFF_ 4096
#define NB_  2

// ---------------- device scratch (no allocations allowed) ----------------
__device__ __half g_wqkv[NB_][3 * DD * DD];        // [sq;sk;sv] stacked rows
__device__ __half g_w1m [NB_][5][DD * DD];         // so,cq,ck,cv,co
__device__ __half g_wf1 [NB_][DFF_ * DD];
__device__ __half g_wf2 [NB_][DD * DFF_];
__device__ __half g_ctx [SS * DD];
__device__ float  g_mods[6 * DD];
__device__ __half g_hx  [LL * DD];
__device__ __half g_qkv [LL * 3 * DD];
__device__ float  g_S   [(size_t)HH * LL * LL];    // logits (also reused for cross)
__device__ __half g_P   [(size_t)HH * LL * LL];    // probs
__device__ __half g_att [LL * DD];
__device__ __half g_kc  [SS * DD];
__device__ __half g_vc  [SS * DD];
__device__ __half g_h1  [LL * DFF_];

// ---------------- small helpers ----------------
DI float warp_sum(float v) {
#pragma unroll
    for (int o = 16; o; o >>= 1) v += __shfl_xor_sync(0xffffffffu, v, o);
    return v;
}
DI float warp_max(float v) {
#pragma unroll
    for (int o = 16; o; o >>= 1) v = fmaxf(v, __shfl_xor_sync(0xffffffffu, v, o));
    return v;
}

// cp.async 16B with zero-fill when !full (src-size = 0 reads nothing)
DI void cp16(void* smem, const void* gmem, bool full) {
    unsigned s = (unsigned)__cvta_generic_to_shared(smem);
    int sz = full ? 16 : 0;
    asm volatile("cp.async.cg.shared.global [%0], [%1], 16, %2;\n"
                 :: "r"(s), "l"(gmem), "r"(sz));
}
DI void cp_commit() { asm volatile("cp.async.commit_group;\n"); }
DI void cp_wait1()  { asm volatile("cp.async.wait_group 1;\n"); }

// fp32 -> fp16 convert (n even)
__global__ void k_convert(const float* __restrict__ s, __half* __restrict__ d, int n) {
    int i = (blockIdx.x * blockDim.x + threadIdx.x) * 2;
    if (i < n) {
        float2 v = *(const float2*)(s + i);
        __half2 o;
        o.x = __float2half(v.x);
        o.y = __float2half(v.y);
        *(__half2*)(d + i) = o;
    }
}

// mods = t @ W^T + b  (W: [rows, 1024]); warp per row, 8 warps/block
__global__ void k_mods(const float* __restrict__ t, const float* __restrict__ W,
                       const float* __restrict__ b, float* __restrict__ out, int rows) {
    int warp = (blockIdx.x * blockDim.x + threadIdx.x) >> 5;
    int lane = threadIdx.x & 31;
    if (warp >= rows) return;
    const float* w = W + (size_t)warp * DD;
    float s = 0.f;
#pragma unroll 8
    for (int k = lane; k < DD; k += 32) s += t[k] * w[k];
    s = warp_sum(s);
    if (lane == 0) out[warp] = s + b[warp];
}

// hx = ln(x) * (1 + sc) + sh   (sc_off < 0 -> plain ln).  1 block per row, 256 thr.
__global__ void k_lnmod(const float* __restrict__ x, const float* __restrict__ mods,
                        int sh_off, int sc_off, __half* __restrict__ out) {
    int l = blockIdx.x;
    const float* xr = x + (size_t)l * DD;
    int t = threadIdx.x;
    float v[4];
    float s = 0.f;
#pragma unroll
    for (int i = 0; i < 4; i++) { v[i] = xr[t + 256 * i]; s += v[i]; }
    __shared__ float red1[8], red2[8];
    s = warp_sum(s);
    if ((t & 31) == 0) red1[t >> 5] = s;
    __syncthreads();
    float tot = 0.f;
#pragma unroll
    for (int i = 0; i < 8; i++) tot += red1[i];
    float mean = tot * (1.f / DD);
    float s2 = 0.f;
#pragma unroll
    for (int i = 0; i < 4; i++) { float d = v[i] - mean; s2 += d * d; }
    s2 = warp_sum(s2);
    if ((t & 31) == 0) red2[t >> 5] = s2;
    __syncthreads();
    float vtot = 0.f;
#pragma unroll
    for (int i = 0; i < 8; i++) vtot += red2[i];
    float rstd = rsqrtf(vtot * (1.f / DD) + 1e-6f);
#pragma unroll
    for (int i = 0; i < 4; i++) {
        int d = t + 256 * i;
        float xn = (v[i] - mean) * rstd;
        float h = xn;
        if (sc_off >= 0) h = xn * (1.f + mods[sc_off + d]) + mods[sh_off + d];
        out[(size_t)l * DD + d] = __float2half(h);
    }
}

// RoPE in-place on q,k sections of qkv (fp16 [L x 3072]); rope fp32 [L x 64]
__global__ void k_rope(__half* __restrict__ qkv, const float* __restrict__ rope) {
    int idx = blockIdx.x * blockDim.x + threadIdx.x;   // L*16*32 threads
    int j = idx & 31;
    int h = (idx >> 5) & 15;
    int l = idx >> 9;
    if (l >= LL) return;
    float e0 = rope[l * 64 + j], e1 = rope[l * 64 + j + 32];
    float c0 = cosf(e0), s0 = sinf(e0), c1 = cosf(e1), s1 = sinf(e1);
    size_t base = (size_t)l * (3 * DD) + h * 64 + j;
#pragma unroll
    for (int qk = 0; qk < 2; qk++) {
        size_t p = base + qk * DD;
        float a = __half2float(qkv[p]);
        float b = __half2float(qkv[p + 32]);
        qkv[p]      = __float2half(a * c0 - b * s0);
        qkv[p + 32] = __float2half(b * c1 + a * s1);
    }
}

// row softmax: P = softmax(S * scale); 1 block per row; PER = C/256
template <int PER>
__global__ void k_softmax(const float* __restrict__ Sm, __half* __restrict__ P,
                          int C, float scale) {
    size_t row = blockIdx.x;
    const float* r = Sm + row * C;
    __half* o = P + row * C;
    int t = threadIdx.x;
    float vals[PER];
    float mx = -1e30f;
#pragma unroll
    for (int i = 0; i < PER; i++) { vals[i] = r[t + 256 * i] * scale; mx = fmaxf(mx, vals[i]); }
    __shared__ float red[8];
    mx = warp_max(mx);
    if ((t & 31) == 0) red[t >> 5] = mx;
    __syncthreads();
    float m = -1e30f;
#pragma unroll
    for (int i = 0; i < 8; i++) m = fmaxf(m, red[i]);
    float s = 0.f;
#pragma unroll
    for (int i = 0; i < PER; i++) { vals[i] = __expf(vals[i] - m); s += vals[i]; }
    __syncthreads();
    s = warp_sum(s);
    if ((t & 31) == 0) red[t >> 5] = s;
    __syncthreads();
    float tot = 0.f;
#pragma unroll
    for (int i = 0; i < 8; i++) tot += red[i];
    float inv = 1.f / tot;
#pragma unroll
    for (int i = 0; i < PER; i++) o[t + 256 * i] = __float2half(vals[i] * inv);
}

// ---------------- generic fp16 mma GEMM, 2-stage cp.async pipeline ----------
// C[M,N] = A[M,K] @ op(B),   BT=true:  B is [N,K] (k-contig)  -> A @ B^T
//                            BT=false: B is [K,N] (n-contig)  -> A @ B
// MODE 0: store fp32
// MODE 1: store fp16 (+bias if given)
// MODE 2: fp32  out = R + gate*(acc+bias)   (gate/bias may be null)
// MODE 3: fp16  out = gelu_exact(acc+bias)
// Requires: K % 32 == 0 per launch (true for all call sites).
#define BM 128
#define BN 128
#define BKk 32

template <int MODE, bool BT>
__global__ void __launch_bounds__(256) k_gemm(
    const __half* __restrict__ A, int lda, long long Abs,
    const __half* __restrict__ B, int ldb, long long Bbs,
    void* __restrict__ Cp, int ldc, long long Cbs,
    const float* __restrict__ Rp, long long Rbs,
    const float* __restrict__ bias, const float* __restrict__ gate,
    int M, int N, int K)
{
    constexpr int ASTR = BKk + 8;                       // 40
    constexpr int BROWS = BT ? BN : BKk;
    constexpr int BSTR = BT ? (BKk + 8) : (BN + 8);     // 40 / 136
    __shared__ __align__(16) unsigned short As[2][BM * ASTR];
    __shared__ __align__(16) unsigned short Bs[2][BROWS * BSTR];

    int tid = threadIdx.x;
    int lane = tid & 31, warp = tid >> 5;
    int wm = warp & 3, wn = warp >> 2;      // 4 warps M x 2 warps N; warp tile 32x64
    int m0 = blockIdx.y * BM, n0 = blockIdx.x * BN;
    long long z = blockIdx.z;
    A += z * Abs;
    B += z * Bbs;

    float acc[2][8][4];
#pragma unroll
    for (int a = 0; a < 2; a++)
#pragma unroll
        for (int b = 0; b < 8; b++)
#pragma unroll
            for (int c = 0; c < 4; c++) acc[a][b][c] = 0.f;

    auto load_tiles = [&](int buf, int k0) {
        // A tile: 128x32, 512 16B copies
#pragma unroll
        for (int i = 0; i < 2; i++) {
            int v = tid + i * 256;
            int r = v >> 2, c8 = (v & 3) * 8;
            cp16(&As[buf][r * ASTR + c8], A + (size_t)(m0 + r) * lda + k0 + c8,
                 (m0 + r) < M);
        }
        if (BT) {
#pragma unroll
            for (int i = 0; i < 2; i++) {
                int v = tid + i * 256;
                int r = v >> 2, c8 = (v & 3) * 8;
                cp16(&Bs[buf][r * BSTR + c8], B + (size_t)(n0 + r) * ldb + k0 + c8,
                     (n0 + r) < N);
            }
        } else {
            // Bs[32 k][128 n]
#pragma unroll
            for (int i = 0; i < 2; i++) {
                int v = tid + i * 256;
                int r = v >> 4, c8 = (v & 15) * 8;
                cp16(&Bs[buf][r * BSTR + c8], B + (size_t)(k0 + r) * ldb + n0 + c8,
                     (n0 + c8) < N);
            }
        }
    };

    int ntiles = K / BKk;
    load_tiles(0, 0);
    cp_commit();

    for (int t = 0; t < ntiles; t++) {
        int buf = t & 1;
        if (t + 1 < ntiles) load_tiles(buf ^ 1, (t + 1) * BKk);
        cp_commit();
        cp_wait1();
        __syncthreads();

#pragma unroll
        for (int ks = 0; ks < 2; ks++) {
            int kb = ks * 16 + (lane & 3) * 2;
            unsigned af[2][4], bf[8][2];
#pragma unroll
            for (int mi = 0; mi < 2; mi++) {
                int r = wm * 32 + mi * 16 + (lane >> 2);
                af[mi][0] = *(const unsigned*)&As[buf][r * ASTR + kb];
                af[mi][1] = *(const unsigned*)&As[buf][(r + 8) * ASTR + kb];
                af[mi][2] = *(const unsigned*)&As[buf][r * ASTR + kb + 8];
                af[mi][3] = *(const unsigned*)&As[buf][(r + 8) * ASTR + kb + 8];
            }
#pragma unroll
            for (int ni = 0; ni < 8; ni++) {
                int c = wn * 64 + ni * 8 + (lane >> 2);
                if (BT) {
                    bf[ni][0] = *(const unsigned*)&Bs[buf][c * BSTR + kb];
                    bf[ni][1] = *(const unsigned*)&Bs[buf][c * BSTR + kb + 8];
                } else {
                    unsigned lo0 = Bs[buf][kb * BSTR + c];
                    unsigned hi0 = Bs[buf][(kb + 1) * BSTR + c];
                    unsigned lo1 = Bs[buf][(kb + 8) * BSTR + c];
                    unsigned hi1 = Bs[buf][(kb + 9) * BSTR + c];
                    bf[ni][0] = lo0 | (hi0 << 16);
                    bf[ni][1] = lo1 | (hi1 << 16);
                }
            }
#pragma unroll
            for (int mi = 0; mi < 2; mi++)
#pragma unroll
                for (int ni = 0; ni < 8; ni++) {
                    asm volatile(
                        "mma.sync.aligned.m16n8k16.row.col.f32.f16.f16.f32 "
                        "{%0,%1,%2,%3}, {%4,%5,%6,%7}, {%8,%9}, {%0,%1,%2,%3};\n"
                        : "+f"(acc[mi][ni][0]), "+f"(acc[mi][ni][1]),
                          "+f"(acc[mi][ni][2]), "+f"(acc[mi][ni][3])
                        : "r"(af[mi][0]), "r"(af[mi][1]), "r"(af[mi][2]), "r"(af[mi][3]),
                          "r"(bf[ni][0]), "r"(bf[ni][1]));
                }
        }
        __syncthreads();
    }

    // epilogue
#pragma unroll
    for (int mi = 0; mi < 2; mi++)
#pragma unroll
        for (int ni = 0; ni < 8; ni++) {
            int m = m0 + wm * 32 + mi * 16 + (lane >> 2);
            int n = n0 + wn * 64 + ni * 8 + (lane & 3) * 2;
            if (n >= N) continue;
#pragma unroll
            for (int rr = 0; rr < 2; rr++) {
                int mm = m + rr * 8;
                if (mm >= M) continue;
                float v0 = acc[mi][ni][rr * 2 + 0];
                float v1 = acc[mi][ni][rr * 2 + 1];
                size_t off = (size_t)mm * ldc + n;
                if (MODE == 0) {
                    float* C = (float*)Cp + z * Cbs;
                    C[off] = v0; C[off + 1] = v1;
                } else if (MODE == 1) {
                    if (bias) { v0 += bias[n]; v1 += bias[n + 1]; }
                    __half* C = (__half*)Cp + z * Cbs;
                    __half2 o; o.x = __float2half(v0); o.y = __float2half(v1);
                    *(__half2*)&C[off] = o;
                } else if (MODE == 2) {
                    float b0 = bias ? bias[n] : 0.f, b1 = bias ? bias[n + 1] : 0.f;
                    float g0 = gate ? gate[n] : 1.f, g1 = gate ? gate[n + 1] : 1.f;
                    float* C = (float*)Cp + z * Cbs;
                    const float* R = Rp + z * Rbs;
                    C[off]     = R[off]     + g0 * (v0 + b0);
                    C[off + 1] = R[off + 1] + g1 * (v1 + b1);
                } else {
                    float b0 = bias ? bias[n] : 0.f, b1 = bias ? bias[n + 1] : 0.f;
                    v0 += b0; v1 += b1;
                    v0 = 0.5f * v0 * (1.f + erff(v0 * 0.70710678118f));
                    v1 = 0.5f * v1 * (1.f + erff(v1 * 0.70710678118f));
                    __half* C = (__half*)Cp + z * Cbs;
                    __half2 o; o.x = __float2half(v0); o.y = __float2half(v1);
                    *(__half2*)&C[off] = o;
                }
            }
        }
}

// ---------------- host helpers ----------------
template <int MODE, bool BT>
static void gemm(const __half* A, int lda, long long Abs,
                 const __half* B, int ldb, long long Bbs,
                 void* C, int ldc, long long Cbs,
                 const float* R, long long Rbs,
                 const float* bias, const float* gate,
                 int M, int N, int K, int batch)
{
    dim3 g((N + BN - 1) / BN, (M + BM - 1) / BM, batch);
    k_gemm<MODE, BT><<<g, 256>>>(A, lda, Abs, B, ldb, Bbs, C, ldc, Cbs, R, Rbs, bias, gate, M, N, K);
}

static void conv(const float* s, __half* d, int n) {
    k_convert<<<(n / 2 + 255) / 256, 256>>>(s, d, n);
}

extern "C" void kernel_launch(void* const* d_in, const int* in_sizes, int n_in,
                              void* d_out, int out_size) {
    (void)in_sizes; (void)n_in; (void)out_size;
    const float* x_in = (const float*)d_in[0];
    const float* temb = (const float*)d_in[1];
    const float* ctxf = (const float*)d_in[2];
    const float* rope = (const float*)d_in[3];
    const float* adaW = (const float*)d_in[4];
    const float* adab = (const float*)d_in[5];
    const float* sqW  = (const float*)d_in[6];
    const float* skW  = (const float*)d_in[7];
    const float* svW  = (const float*)d_in[8];
    const float* soW  = (const float*)d_in[9];
    const float* sob  = (const float*)d_in[10];
    const float* cqW  = (const float*)d_in[11];
    const float* ckW  = (const float*)d_in[12];
    const float* cvW  = (const float*)d_in[13];
    const float* coW  = (const float*)d_in[14];
    const float* cob  = (const float*)d_in[15];
    const float* f1W  = (const float*)d_in[16];
    const float* f1b  = (const float*)d_in[17];
    const float* f2W  = (const float*)d_in[18];
    const float* f2b  = (const float*)d_in[19];
    float* x = (float*)d_out;

    void* p;
    cudaGetSymbolAddress(&p, g_wqkv); __half* wqkv = (__half*)p;
    cudaGetSymbolAddress(&p, g_w1m);  __half* w1m  = (__half*)p;
    cudaGetSymbolAddress(&p, g_wf1);  __half* wf1  = (__half*)p;
    cudaGetSymbolAddress(&p, g_wf2);  __half* wf2  = (__half*)p;
    cudaGetSymbolAddress(&p, g_ctx);  __half* ctxb = (__half*)p;
    cudaGetSymbolAddress(&p, g_mods); float* mods = (float*)p;
    cudaGetSymbolAddress(&p, g_hx);   __half* hx   = (__half*)p;
    cudaGetSymbolAddress(&p, g_qkv);  __half* qkv  = (__half*)p;
    cudaGetSymbolAddress(&p, g_S);    float* Sb = (float*)p;
    cudaGetSymbolAddress(&p, g_P);    __half* Pb   = (__half*)p;
    cudaGetSymbolAddress(&p, g_att);  __half* att  = (__half*)p;
    cudaGetSymbolAddress(&p, g_kc);   __half* kc   = (__half*)p;
    cudaGetSymbolAddress(&p, g_vc);   __half* vc   = (__half*)p;
    cudaGetSymbolAddress(&p, g_h1);   __half* h1   = (__half*)p;

    // x := input residual stream (lives in d_out)
    cudaMemcpyAsync(x, x_in, (size_t)LL * DD * sizeof(float), cudaMemcpyDeviceToDevice);

    // convert weights / context to fp16
    conv(ctxf, ctxb, SS * DD);
    for (int i = 0; i < NB_; i++) {
        size_t wo = (size_t)i * 3 * DD * DD;
        conv(sqW + (size_t)i * DD * DD, wqkv + wo,               DD * DD);
        conv(skW + (size_t)i * DD * DD, wqkv + wo + DD * DD,     DD * DD);
        conv(svW + (size_t)i * DD * DD, wqkv + wo + 2 * DD * DD, DD * DD);
        conv(soW + (size_t)i * DD * DD, w1m + ((size_t)i * 5 + 0) * DD * DD, DD * DD);
        conv(cqW + (size_t)i * DD * DD, w1m + ((size_t)i * 5 + 1) * DD * DD, DD * DD);
        conv(ckW + (size_t)i * DD * DD, w1m + ((size_t)i * 5 + 2) * DD * DD, DD * DD);
        conv(cvW + (size_t)i * DD * DD, w1m + ((size_t)i * 5 + 3) * DD * DD, DD * DD);
        conv(coW + (size_t)i * DD * DD, w1m + ((size_t)i * 5 + 4) * DD * DD, DD * DD);
        conv(f1W + (size_t)i * DFF_ * DD, wf1 + (size_t)i * DFF_ * DD, DFF_ * DD);
        conv(f2W + (size_t)i * DD * DFF_, wf2 + (size_t)i * DD * DFF_, DD * DFF_);
    }

    const float scale = 0.125f;  // HD^-0.5

    for (int i = 0; i < NB_; i++) {
        // AdaLN mods: [6*1024] = sh_msa, sc_msa, g_msa, sh_mlp, sc_mlp, g_mlp
        k_mods<<<(6 * DD) / 8, 256>>>(temb, adaW + (size_t)i * 6 * DD * DD,
                                      adab + (size_t)i * 6 * DD, mods, 6 * DD);

        // ---- self attention ----
        k_lnmod<<<LL, 256>>>(x, mods, /*sh*/0, /*sc*/DD, hx);
        gemm<1, true>(hx, DD, 0, wqkv + (size_t)i * 3 * DD * DD, DD, 0,
                      qkv, 3 * DD, 0, nullptr, 0, nullptr, nullptr, LL, 3 * DD, DD, 1);
        k_rope<<<(LL * HH * 32) / 256, 256>>>(qkv, rope);
        // S = Q @ K^T per head
        gemm<0, true>(qkv, 3 * DD, HDM, qkv + DD, 3 * DD, HDM,
                      Sb, LL, (long long)LL * LL, nullptr, 0, nullptr, nullptr, LL, LL, HDM, HH);
        k_softmax<12><<<HH * LL, 256>>>(Sb, Pb, LL, scale);
        // O = P @ V per head
        gemm<1, false>(Pb, LL, (long long)LL * LL, qkv + 2 * DD, 3 * DD, HDM,
                       att, DD, HDM, nullptr, 0, nullptr, nullptr, LL, HDM, LL, HH);
        // x += g_msa * (O @ soW^T + sob)
        gemm<2, true>(att, DD, 0, w1m + ((size_t)i * 5 + 0) * DD * DD, DD, 0,
                      x, DD, 0, x, 0, sob + (size_t)i * DD, mods + 2 * DD, LL, DD, DD, 1);

        // ---- cross attention ----
        k_lnmod<<<LL, 256>>>(x, mods, -1, -1, hx);
        gemm<1, true>(hx, DD, 0, w1m + ((size_t)i * 5 + 1) * DD * DD, DD, 0,
                      qkv, DD, 0, nullptr, 0, nullptr, nullptr, LL, DD, DD, 1);
        gemm<1, true>(ctxb, DD, 0, w1m + ((size_t)i * 5 + 2) * DD * DD, DD, 0,
                      kc, DD, 0, nullptr, 0, nullptr, nullptr, SS, DD, DD, 1);
        gemm<1, true>(ctxb, DD, 0, w1m + ((size_t)i * 5 + 3) * DD * DD, DD, 0,
                      vc, DD, 0, nullptr, 0, nullptr, nullptr, SS, DD, DD, 1);
        gemm<0, true>(qkv, DD, HDM, kc, DD, HDM,
                      Sb, SS, (long long)LL * SS, nullptr, 0, nullptr, nullptr, LL, SS, HDM, HH);
        k_softmax<2><<<HH * LL, 256>>>(Sb, Pb, SS, scale);
        gemm<1, false>(Pb, SS, (long long)LL * SS, vc, DD, HDM,
                       att, DD, HDM, nullptr, 0, nullptr, nullptr, LL, HDM, SS, HH);
        // x += O @ coW^T + cob
        gemm<2, true>(att, DD, 0, w1m + ((size_t)i * 5 + 4) * DD * DD, DD, 0,
                      x, DD, 0, x, 0, cob + (size_t)i * DD, nullptr, LL, DD, DD, 1);

        // ---- MLP ----
        k_lnmod<<<LL, 256>>>(x, mods, /*sh_mlp*/3 * DD, /*sc_mlp*/4 * DD, hx);
        gemm<3, true>(hx, DD, 0, wf1 + (size_t)i * DFF_ * DD, DD, 0,
                      h1, DFF_, 0, nullptr, 0, f1b + (size_t)i * DFF_, nullptr, LL, DFF_, DD, 1);
        gemm<2, true>(h1, DFF_, 0, wf2 + (size_t)i * DD * DFF_, DFF_, 0,
                      x, DD, 0, x, 0, f2b + (size_t)i * DD, mods + 5 * DD, LL, DD, DFF_, 1);
    }
}

// round 9
// speedup vs baseline: 1.4399x; 1.4399x over previous
#include <cuda_runtime.h>
#include <cuda_fp16.h>

#define DI __device__ __forceinline__

// ---------------- problem constants ----------------
#define LL   3072
#define DD   1024
#define HH   16
#define HDM  64
#define SS   512
#define DFF_ 4096
#define NB_  2

// ---------------- device scratch (no allocations allowed) ----------------
__device__ __half g_wqkv[NB_][3 * DD * DD];        // [sq;sk;sv] stacked rows
__device__ __half g_w1m [NB_][5][DD * DD];         // so,cq,ck,cv,co
__device__ __half g_wf1 [NB_][DFF_ * DD];
__device__ __half g_wf2 [NB_][DD * DFF_];
__device__ __half g_ctx [SS * DD];
__device__ float  g_mods[6 * DD];
__device__ __half g_hx  [LL * DD];
__device__ __half g_qkv [LL * 3 * DD];
__device__ __half g_att [LL * DD];
__device__ __half g_kc  [SS * DD];
__device__ __half g_vc  [SS * DD];
__device__ __half g_h1  [LL * DFF_];

// ---------------- small helpers ----------------
DI float warp_sum(float v) {
#pragma unroll
    for (int o = 16; o; o >>= 1) v += __shfl_xor_sync(0xffffffffu, v, o);
    return v;
}
DI float warp_max(float v) {
#pragma unroll
    for (int o = 16; o; o >>= 1) v = fmaxf(v, __shfl_xor_sync(0xffffffffu, v, o));
    return v;
}

// cp.async 16B with zero-fill when !full (src-size = 0 reads nothing)
DI void cp16(void* smem, const void* gmem, bool full) {
    unsigned s = (unsigned)__cvta_generic_to_shared(smem);
    int sz = full ? 16 : 0;
    asm volatile("cp.async.cg.shared.global [%0], [%1], 16, %2;\n"
                 :: "r"(s), "l"(gmem), "r"(sz));
}
DI void cp_commit() { asm volatile("cp.async.commit_group;\n"); }
DI void cp_wait1()  { asm volatile("cp.async.wait_group 1;\n"); }

DI void mma16816(float* c, const unsigned* a, unsigned b0, unsigned b1) {
    asm volatile(
        "mma.sync.aligned.m16n8k16.row.col.f32.f16.f16.f32 "
        "{%0,%1,%2,%3}, {%4,%5,%6,%7}, {%8,%9}, {%0,%1,%2,%3};\n"
        : "+f"(c[0]), "+f"(c[1]), "+f"(c[2]), "+f"(c[3])
        : "r"(a[0]), "r"(a[1]), "r"(a[2]), "r"(a[3]), "r"(b0), "r"(b1));
}

DI unsigned packh2(float x, float y) {
    __half2 h; h.x = __float2half(x); h.y = __float2half(y);
    return *(unsigned*)&h;
}

// fp32 -> fp16 convert (n even)
__global__ void k_convert(const float* __restrict__ s, __half* __restrict__ d, int n) {
    int i = (blockIdx.x * blockDim.x + threadIdx.x) * 2;
    if (i < n) {
        float2 v = *(const float2*)(s + i);
        __half2 o;
        o.x = __float2half(v.x);
        o.y = __float2half(v.y);
        *(__half2*)(d + i) = o;
    }
}

// mods = t @ W^T + b  (W: [rows, 1024]); warp per row, 8 warps/block
__global__ void k_mods(const float* __restrict__ t, const float* __restrict__ W,
                       const float* __restrict__ b, float* __restrict__ out, int rows) {
    int warp = (blockIdx.x * blockDim.x + threadIdx.x) >> 5;
    int lane = threadIdx.x & 31;
    if (warp >= rows) return;
    const float* w = W + (size_t)warp * DD;
    float s = 0.f;
#pragma unroll 8
    for (int k = lane; k < DD; k += 32) s += t[k] * w[k];
    s = warp_sum(s);
    if (lane == 0) out[warp] = s + b[warp];
}

// hx = ln(x) * (1 + sc) + sh   (sc_off < 0 -> plain ln).  1 block per row, 256 thr.
__global__ void k_lnmod(const float* __restrict__ x, const float* __restrict__ mods,
                        int sh_off, int sc_off, __half* __restrict__ out) {
    int l = blockIdx.x;
    const float* xr = x + (size_t)l * DD;
    int t = threadIdx.x;
    float v[4];
    float s = 0.f;
#pragma unroll
    for (int i = 0; i < 4; i++) { v[i] = xr[t + 256 * i]; s += v[i]; }
    __shared__ float red1[8], red2[8];
    s = warp_sum(s);
    if ((t & 31) == 0) red1[t >> 5] = s;
    __syncthreads();
    float tot = 0.f;
#pragma unroll
    for (int i = 0; i < 8; i++) tot += red1[i];
    float mean = tot * (1.f / DD);
    float s2 = 0.f;
#pragma unroll
    for (int i = 0; i < 4; i++) { float d = v[i] - mean; s2 += d * d; }
    s2 = warp_sum(s2);
    if ((t & 31) == 0) red2[t >> 5] = s2;
    __syncthreads();
    float vtot = 0.f;
#pragma unroll
    for (int i = 0; i < 8; i++) vtot += red2[i];
    float rstd = rsqrtf(vtot * (1.f / DD) + 1e-6f);
#pragma unroll
    for (int i = 0; i < 4; i++) {
        int d = t + 256 * i;
        float xn = (v[i] - mean) * rstd;
        float h = xn;
        if (sc_off >= 0) h = xn * (1.f + mods[sc_off + d]) + mods[sh_off + d];
        out[(size_t)l * DD + d] = __float2half(h);
    }
}

// RoPE in-place on q,k sections of qkv (fp16 [L x 3072]); rope fp32 [L x 64]
__global__ void k_rope(__half* __restrict__ qkv, const float* __restrict__ rope) {
    int idx = blockIdx.x * blockDim.x + threadIdx.x;   // L*16*32 threads
    int j = idx & 31;
    int h = (idx >> 5) & 15;
    int l = idx >> 9;
    if (l >= LL) return;
    float e0 = rope[l * 64 + j], e1 = rope[l * 64 + j + 32];
    float c0 = cosf(e0), s0 = sinf(e0), c1 = cosf(e1), s1 = sinf(e1);
    size_t base = (size_t)l * (3 * DD) + h * 64 + j;
#pragma unroll
    for (int qk = 0; qk < 2; qk++) {
        size_t p = base + qk * DD;
        float a = __half2float(qkv[p]);
        float b = __half2float(qkv[p + 32]);
        qkv[p]      = __float2half(a * c0 - b * s0);
        qkv[p + 32] = __float2half(b * c1 + a * s1);
    }
}

// ---------------- fused flash attention ----------------
// One block: 128 q-rows x one head. 256 threads = 8 warps, 16 rows/warp.
// Q fragments in registers (pre-scaled); K/V 64-row tiles double-buffered cp.async.
// Online softmax in fp32; O accumulated fp32; output fp16.
__global__ void __launch_bounds__(256) k_flash(
    const __half* __restrict__ Qp, int q_rs,
    const __half* __restrict__ Kp, int k_rs,
    const __half* __restrict__ Vp, int v_rs,
    __half* __restrict__ Op, int o_rs,
    int kv_len, float scale)
{
    constexpr int STR = 72;   // smem row stride in halves (144B, conflict-free)
    __shared__ __align__(16) __half Ks[2][64 * STR];
    __shared__ __align__(16) __half Vs[2][64 * STR];

    const int h = blockIdx.y;
    const int q0 = blockIdx.x * 128;
    const __half* Q = Qp + h * HDM;
    const __half* K = Kp + h * HDM;
    const __half* V = Vp + h * HDM;
    __half* O = Op + h * HDM;

    int tid = threadIdx.x, lane = tid & 31, warp = tid >> 5;
    int row0 = q0 + warp * 16 + (lane >> 2);   // rows row0, row0+8

    // Q fragments, pre-scaled by `scale` (exact for 0.125 in fp16)
    __half2 hs = __half2half2(__float2half(scale));
    unsigned qf[4][4];
#pragma unroll
    for (int ks = 0; ks < 4; ks++) {
        int k = ks * 16 + (lane & 3) * 2;
        __half2 v0 = __hmul2(*(const __half2*)&Q[(size_t)row0 * q_rs + k], hs);
        __half2 v1 = __hmul2(*(const __half2*)&Q[(size_t)(row0 + 8) * q_rs + k], hs);
        __half2 v2 = __hmul2(*(const __half2*)&Q[(size_t)row0 * q_rs + k + 8], hs);
        __half2 v3 = __hmul2(*(const __half2*)&Q[(size_t)(row0 + 8) * q_rs + k + 8], hs);
        qf[ks][0] = *(unsigned*)&v0;
        qf[ks][1] = *(unsigned*)&v1;
        qf[ks][2] = *(unsigned*)&v2;
        qf[ks][3] = *(unsigned*)&v3;
    }

    auto load_kv = [&](int buf, int t0) {
#pragma unroll
        for (int i = 0; i < 2; i++) {
            int v = tid + i * 256;
            int r = v >> 3, c = (v & 7) * 8;
            cp16(&Ks[buf][r * STR + c], K + (size_t)(t0 + r) * k_rs + c, true);
        }
#pragma unroll
        for (int i = 0; i < 2; i++) {
            int v = tid + i * 256;
            int r = v >> 3, c = (v & 7) * 8;
            cp16(&Vs[buf][r * STR + c], V + (size_t)(t0 + r) * v_rs + c, true);
        }
    };

    float o[8][4];
#pragma unroll
    for (int i = 0; i < 8; i++)
#pragma unroll
        for (int j = 0; j < 4; j++) o[i][j] = 0.f;
    float m0 = -1e30f, m1 = -1e30f, l0 = 0.f, l1 = 0.f;

    int nt = kv_len / 64;
    load_kv(0, 0);
    cp_commit();

    for (int t = 0; t < nt; t++) {
        int buf = t & 1;
        if (t + 1 < nt) load_kv(buf ^ 1, (t + 1) * 64);
        cp_commit();
        cp_wait1();
        __syncthreads();

        // ---- S = (Q*scale) @ K^T : 128 x 64 tile ----
        float s[8][4];
#pragma unroll
        for (int i = 0; i < 8; i++)
#pragma unroll
            for (int j = 0; j < 4; j++) s[i][j] = 0.f;
        int kb = (lane & 3) * 2;
        int nrow = lane >> 2;
#pragma unroll
        for (int ks = 0; ks < 4; ks++) {
#pragma unroll
            for (int ni = 0; ni < 8; ni++) {
                unsigned b0 = *(const unsigned*)&Ks[buf][(ni * 8 + nrow) * STR + ks * 16 + kb];
                unsigned b1 = *(const unsigned*)&Ks[buf][(ni * 8 + nrow) * STR + ks * 16 + kb + 8];
                mma16816(s[ni], qf[ks], b0, b1);
            }
        }

        // ---- online softmax ----
        float mn0 = -1e30f, mn1 = -1e30f;
#pragma unroll
        for (int ni = 0; ni < 8; ni++) {
            mn0 = fmaxf(mn0, fmaxf(s[ni][0], s[ni][1]));
            mn1 = fmaxf(mn1, fmaxf(s[ni][2], s[ni][3]));
        }
        mn0 = fmaxf(mn0, __shfl_xor_sync(0xffffffffu, mn0, 1));
        mn0 = fmaxf(mn0, __shfl_xor_sync(0xffffffffu, mn0, 2));
        mn1 = fmaxf(mn1, __shfl_xor_sync(0xffffffffu, mn1, 1));
        mn1 = fmaxf(mn1, __shfl_xor_sync(0xffffffffu, mn1, 2));
        float nm0 = fmaxf(m0, mn0), nm1 = fmaxf(m1, mn1);
        float a0 = __expf(m0 - nm0), a1 = __expf(m1 - nm1);
        m0 = nm0; m1 = nm1;
        float rs0 = 0.f, rs1 = 0.f;
#pragma unroll
        for (int ni = 0; ni < 8; ni++) {
            s[ni][0] = __expf(s[ni][0] - nm0);
            s[ni][1] = __expf(s[ni][1] - nm0);
            s[ni][2] = __expf(s[ni][2] - nm1);
            s[ni][3] = __expf(s[ni][3] - nm1);
            rs0 += s[ni][0] + s[ni][1];
            rs1 += s[ni][2] + s[ni][3];
        }
        rs0 += __shfl_xor_sync(0xffffffffu, rs0, 1);
        rs0 += __shfl_xor_sync(0xffffffffu, rs0, 2);
        rs1 += __shfl_xor_sync(0xffffffffu, rs1, 1);
        rs1 += __shfl_xor_sync(0xffffffffu, rs1, 2);
        l0 = l0 * a0 + rs0;
        l1 = l1 * a1 + rs1;
#pragma unroll
        for (int ni = 0; ni < 8; ni++) {
            o[ni][0] *= a0; o[ni][1] *= a0;
            o[ni][2] *= a1; o[ni][3] *= a1;
        }

        // ---- pack P to fp16 A-fragments ----
        unsigned pf[4][4];
#pragma unroll
        for (int j = 0; j < 4; j++) {
            pf[j][0] = packh2(s[2 * j][0], s[2 * j][1]);
            pf[j][1] = packh2(s[2 * j][2], s[2 * j][3]);
            pf[j][2] = packh2(s[2 * j + 1][0], s[2 * j + 1][1]);
            pf[j][3] = packh2(s[2 * j + 1][2], s[2 * j + 1][3]);
        }

        // ---- O += P @ V ----
#pragma unroll
        for (int j = 0; j < 4; j++) {
            int k = j * 16 + kb;
#pragma unroll
            for (int ni = 0; ni < 8; ni++) {
                int n = ni * 8 + nrow;
                unsigned b0 = packh2(__half2float(Vs[buf][k * STR + n]),
                                     __half2float(Vs[buf][(k + 1) * STR + n]));
                unsigned b1 = packh2(__half2float(Vs[buf][(k + 8) * STR + n]),
                                     __half2float(Vs[buf][(k + 9) * STR + n]));
                mma16816(o[ni], pf[j], b0, b1);
            }
        }
        __syncthreads();
    }

    // ---- finalize: O /= l, store fp16 ----
    float inv0 = 1.f / l0, inv1 = 1.f / l1;
#pragma unroll
    for (int ni = 0; ni < 8; ni++) {
        int d = ni * 8 + (lane & 3) * 2;
        __half2 w0; w0.x = __float2half(o[ni][0] * inv0); w0.y = __float2half(o[ni][1] * inv0);
        __half2 w1; w1.x = __float2half(o[ni][2] * inv1); w1.y = __float2half(o[ni][3] * inv1);
        *(__half2*)&O[(size_t)row0 * o_rs + d] = w0;
        *(__half2*)&O[(size_t)(row0 + 8) * o_rs + d] = w1;
    }
}

// ---------------- generic fp16 mma GEMM, 2-stage cp.async pipeline ----------
// C[M,N] = A[M,K] @ op(B),   BT=true:  B is [N,K] (k-contig)  -> A @ B^T
// MODE 0: store fp32
// MODE 1: store fp16 (+bias if given)
// MODE 2: fp32  out = R + gate*(acc+bias)   (gate/bias may be null)
// MODE 3: fp16  out = gelu_exact(acc+bias)
#define BM 128
#define BN 128
#define BKk 32

template <int MODE, bool BT>
__global__ void __launch_bounds__(256) k_gemm(
    const __half* __restrict__ A, int lda, long long Abs,
    const __half* __restrict__ B, int ldb, long long Bbs,
    void* __restrict__ Cp, int ldc, long long Cbs,
    const float* __restrict__ Rp, long long Rbs,
    const float* __restrict__ bias, const float* __restrict__ gate,
    int M, int N, int K)
{
    constexpr int ASTR = BKk + 8;                       // 40
    constexpr int BROWS = BT ? BN : BKk;
    constexpr int BSTR = BT ? (BKk + 8) : (BN + 8);     // 40 / 136
    __shared__ __align__(16) unsigned short As[2][BM * ASTR];
    __shared__ __align__(16) unsigned short Bs[2][BROWS * BSTR];

    int tid = threadIdx.x;
    int lane = tid & 31, warp = tid >> 5;
    int wm = warp & 3, wn = warp >> 2;      // 4 warps M x 2 warps N; warp tile 32x64
    int m0 = blockIdx.y * BM, n0 = blockIdx.x * BN;
    long long z = blockIdx.z;
    A += z * Abs;
    B += z * Bbs;

    float acc[2][8][4];
#pragma unroll
    for (int a = 0; a < 2; a++)
#pragma unroll
        for (int b = 0; b < 8; b++)
#pragma unroll
            for (int c = 0; c < 4; c++) acc[a][b][c] = 0.f;

    auto load_tiles = [&](int buf, int k0) {
#pragma unroll
        for (int i = 0; i < 2; i++) {
            int v = tid + i * 256;
            int r = v >> 2, c8 = (v & 3) * 8;
            cp16(&As[buf][r * ASTR + c8], A + (size_t)(m0 + r) * lda + k0 + c8,
                 (m0 + r) < M);
        }
        if (BT) {
#pragma unroll
            for (int i = 0; i < 2; i++) {
                int v = tid + i * 256;
                int r = v >> 2, c8 = (v & 3) * 8;
                cp16(&Bs[buf][r * BSTR + c8], B + (size_t)(n0 + r) * ldb + k0 + c8,
                     (n0 + r) < N);
            }
        } else {
#pragma unroll
            for (int i = 0; i < 2; i++) {
                int v = tid + i * 256;
                int r = v >> 4, c8 = (v & 15) * 8;
                cp16(&Bs[buf][r * BSTR + c8], B + (size_t)(k0 + r) * ldb + n0 + c8,
                     (n0 + c8) < N);
            }
        }
    };

    int ntiles = K / BKk;
    load_tiles(0, 0);
    cp_commit();

    for (int t = 0; t < ntiles; t++) {
        int buf = t & 1;
        if (t + 1 < ntiles) load_tiles(buf ^ 1, (t + 1) * BKk);
        cp_commit();
        cp_wait1();
        __syncthreads();

#pragma unroll
        for (int ks = 0; ks < 2; ks++) {
            int kb = ks * 16 + (lane & 3) * 2;
            unsigned af[2][4], bf[8][2];
#pragma unroll
            for (int mi = 0; mi < 2; mi++) {
                int r = wm * 32 + mi * 16 + (lane >> 2);
                af[mi][0] = *(const unsigned*)&As[buf][r * ASTR + kb];
                af[mi][1] = *(const unsigned*)&As[buf][(r + 8) * ASTR + kb];
                af[mi][2] = *(const unsigned*)&As[buf][r * ASTR + kb + 8];
                af[mi][3] = *(const unsigned*)&As[buf][(r + 8) * ASTR + kb + 8];
            }
#pragma unroll
            for (int ni = 0; ni < 8; ni++) {
                int c = wn * 64 + ni * 8 + (lane >> 2);
                if (BT) {
                    bf[ni][0] = *(const unsigned*)&Bs[buf][c * BSTR + kb];
                    bf[ni][1] = *(const unsigned*)&Bs[buf][c * BSTR + kb + 8];
                } else {
                    unsigned lo0 = Bs[buf][kb * BSTR + c];
                    unsigned hi0 = Bs[buf][(kb + 1) * BSTR + c];
                    unsigned lo1 = Bs[buf][(kb + 8) * BSTR + c];
                    unsigned hi1 = Bs[buf][(kb + 9) * BSTR + c];
                    bf[ni][0] = lo0 | (hi0 << 16);
                    bf[ni][1] = lo1 | (hi1 << 16);
                }
            }
#pragma unroll
            for (int mi = 0; mi < 2; mi++)
#pragma unroll
                for (int ni = 0; ni < 8; ni++)
                    mma16816(acc[mi][ni], af[mi], bf[ni][0], bf[ni][1]);
        }
        __syncthreads();
    }

    // epilogue
#pragma unroll
    for (int mi = 0; mi < 2; mi++)
#pragma unroll
        for (int ni = 0; ni < 8; ni++) {
            int m = m0 + wm * 32 + mi * 16 + (lane >> 2);
            int n = n0 + wn * 64 + ni * 8 + (lane & 3) * 2;
            if (n >= N) continue;
#pragma unroll
            for (int rr = 0; rr < 2; rr++) {
                int mm = m + rr * 8;
                if (mm >= M) continue;
                float v0 = acc[mi][ni][rr * 2 + 0];
                float v1 = acc[mi][ni][rr * 2 + 1];
                size_t off = (size_t)mm * ldc + n;
                if (MODE == 0) {
                    float* C = (float*)Cp + z * Cbs;
                    C[off] = v0; C[off + 1] = v1;
                } else if (MODE == 1) {
                    if (bias) { v0 += bias[n]; v1 += bias[n + 1]; }
                    __half* C = (__half*)Cp + z * Cbs;
                    __half2 o; o.x = __float2half(v0); o.y = __float2half(v1);
                    *(__half2*)&C[off] = o;
                } else if (MODE == 2) {
                    float b0 = bias ? bias[n] : 0.f, b1 = bias ? bias[n + 1] : 0.f;
                    float g0 = gate ? gate[n] : 1.f, g1 = gate ? gate[n + 1] : 1.f;
                    float* C = (float*)Cp + z * Cbs;
                    const float* R = Rp + z * Rbs;
                    C[off]     = R[off]     + g0 * (v0 + b0);
                    C[off + 1] = R[off + 1] + g1 * (v1 + b1);
                } else {
                    float b0 = bias ? bias[n] : 0.f, b1 = bias ? bias[n + 1] : 0.f;
                    v0 += b0; v1 += b1;
                    v0 = 0.5f * v0 * (1.f + erff(v0 * 0.70710678118f));
                    v1 = 0.5f * v1 * (1.f + erff(v1 * 0.70710678118f));
                    __half* C = (__half*)Cp + z * Cbs;
                    __half2 o; o.x = __float2half(v0); o.y = __float2half(v1);
                    *(__half2*)&C[off] = o;
                }
            }
        }
}

// ---------------- host helpers ----------------
template <int MODE, bool BT>
static void gemm(const __half* A, int lda, long long Abs,
                 const __half* B, int ldb, long long Bbs,
                 void* C, int ldc, long long Cbs,
                 const float* R, long long Rbs,
                 const float* bias, const float* gate,
                 int M, int N, int K, int batch)
{
    dim3 g((N + BN - 1) / BN, (M + BM - 1) / BM, batch);
    k_gemm<MODE, BT><<<g, 256>>>(A, lda, Abs, B, ldb, Bbs, C, ldc, Cbs, R, Rbs, bias, gate, M, N, K);
}

static void conv(const float* s, __half* d, int n) {
    k_convert<<<(n / 2 + 255) / 256, 256>>>(s, d, n);
}

extern "C" void kernel_launch(void* const* d_in, const int* in_sizes, int n_in,
                              void* d_out, int out_size) {
    (void)in_sizes; (void)n_in; (void)out_size;
    const float* x_in = (const float*)d_in[0];
    const float* temb = (const float*)d_in[1];
    const float* ctxf = (const float*)d_in[2];
    const float* rope = (const float*)d_in[3];
    const float* adaW = (const float*)d_in[4];
    const float* adab = (const float*)d_in[5];
    const float* sqW  = (const float*)d_in[6];
    const float* skW  = (const float*)d_in[7];
    const float* svW  = (const float*)d_in[8];
    const float* soW  = (const float*)d_in[9];
    const float* sob  = (const float*)d_in[10];
    const float* cqW  = (const float*)d_in[11];
    const float* ckW  = (const float*)d_in[12];
    const float* cvW  = (const float*)d_in[13];
    const float* coW  = (const float*)d_in[14];
    const float* cob  = (const float*)d_in[15];
    const float* f1W  = (const float*)d_in[16];
    const float* f1b  = (const float*)d_in[17];
    const float* f2W  = (const float*)d_in[18];
    const float* f2b  = (const float*)d_in[19];
    float* x = (float*)d_out;

    void* p;
    cudaGetSymbolAddress(&p, g_wqkv); __half* wqkv = (__half*)p;
    cudaGetSymbolAddress(&p, g_w1m);  __half* w1m  = (__half*)p;
    cudaGetSymbolAddress(&p, g_wf1);  __half* wf1  = (__half*)p;
    cudaGetSymbolAddress(&p, g_wf2);  __half* wf2  = (__half*)p;
    cudaGetSymbolAddress(&p, g_ctx);  __half* ctxb = (__half*)p;
    cudaGetSymbolAddress(&p, g_mods); float* mods = (float*)p;
    cudaGetSymbolAddress(&p, g_hx);   __half* hx   = (__half*)p;
    cudaGetSymbolAddress(&p, g_qkv);  __half* qkv  = (__half*)p;
    cudaGetSymbolAddress(&p, g_att);  __half* att  = (__half*)p;
    cudaGetSymbolAddress(&p, g_kc);   __half* kc   = (__half*)p;
    cudaGetSymbolAddress(&p, g_vc);   __half* vc   = (__half*)p;
    cudaGetSymbolAddress(&p, g_h1);   __half* h1   = (__half*)p;

    // x := input residual stream (lives in d_out)
    cudaMemcpyAsync(x, x_in, (size_t)LL * DD * sizeof(float), cudaMemcpyDeviceToDevice);

    // convert weights / context to fp16
    conv(ctxf, ctxb, SS * DD);
    for (int i = 0; i < NB_; i++) {
        size_t wo = (size_t)i * 3 * DD * DD;
        conv(sqW + (size_t)i * DD * DD, wqkv + wo,               DD * DD);
        conv(skW + (size_t)i * DD * DD, wqkv + wo + DD * DD,     DD * DD);
        conv(svW + (size_t)i * DD * DD, wqkv + wo + 2 * DD * DD, DD * DD);
        conv(soW + (size_t)i * DD * DD, w1m + ((size_t)i * 5 + 0) * DD * DD, DD * DD);
        conv(cqW + (size_t)i * DD * DD, w1m + ((size_t)i * 5 + 1) * DD * DD, DD * DD);
        conv(ckW + (size_t)i * DD * DD, w1m + ((size_t)i * 5 + 2) * DD * DD, DD * DD);
        conv(cvW + (size_t)i * DD * DD, w1m + ((size_t)i * 5 + 3) * DD * DD, DD * DD);
        conv(coW + (size_t)i * DD * DD, w1m + ((size_t)i * 5 + 4) * DD * DD, DD * DD);
        conv(f1W + (size_t)i * DFF_ * DD, wf1 + (size_t)i * DFF_ * DD, DFF_ * DD);
        conv(f2W + (size_t)i * DD * DFF_, wf2 + (size_t)i * DD * DFF_, DD * DFF_);
    }

    const float scale = 0.125f;  // HD^-0.5

    for (int i = 0; i < NB_; i++) {
        // AdaLN mods: [6*1024] = sh_msa, sc_msa, g_msa, sh_mlp, sc_mlp, g_mlp
        k_mods<<<(6 * DD) / 8, 256>>>(temb, adaW + (size_t)i * 6 * DD * DD,
                                      adab + (size_t)i * 6 * DD, mods, 6 * DD);

        // ---- self attention ----
        k_lnmod<<<LL, 256>>>(x, mods, /*sh*/0, /*sc*/DD, hx);
        gemm<1, true>(hx, DD, 0, wqkv + (size_t)i * 3 * DD * DD, DD, 0,
                      qkv, 3 * DD, 0, nullptr, 0, nullptr, nullptr, LL, 3 * DD, DD, 1);
        k_rope<<<(LL * HH * 32) / 256, 256>>>(qkv, rope);
        // fused flash attention: att = softmax(QK^T/8) V
        k_flash<<<dim3(LL / 128, HH), 256>>>(qkv, 3 * DD, qkv + DD, 3 * DD,
                                             qkv + 2 * DD, 3 * DD, att, DD, LL, scale);
        // x += g_msa * (O @ soW^T + sob)
        gemm<2, true>(att, DD, 0, w1m + ((size_t)i * 5 + 0) * DD * DD, DD, 0,
                      x, DD, 0, x, 0, sob + (size_t)i * DD, mods + 2 * DD, LL, DD, DD, 1);

        // ---- cross attention ----
        k_lnmod<<<LL, 256>>>(x, mods, -1, -1, hx);
        gemm<1, true>(hx, DD, 0, w1m + ((size_t)i * 5 + 1) * DD * DD, DD, 0,
                      qkv, DD, 0, nullptr, 0, nullptr, nullptr, LL, DD, DD, 1);
        gemm<1, true>(ctxb, DD, 0, w1m + ((size_t)i * 5 + 2) * DD * DD, DD, 0,
                      kc, DD, 0, nullptr, 0, nullptr, nullptr, SS, DD, DD, 1);
        gemm<1, true>(ctxb, DD, 0, w1m + ((size_t)i * 5 + 3) * DD * DD, DD, 0,
                      vc, DD, 0, nullptr, 0, nullptr, nullptr, SS, DD, DD, 1);
        k_flash<<<dim3(LL / 128, HH), 256>>>(qkv, DD, kc, DD, vc, DD,
                                             att, DD, SS, scale);
        // x += O @ coW^T + cob
        gemm<2, true>(att, DD, 0, w1m + ((size_t)i * 5 + 4) * DD * DD, DD, 0,
                      x, DD, 0, x, 0, cob + (size_t)i * DD, nullptr, LL, DD, DD, 1);

        // ---- MLP ----
        k_lnmod<<<LL, 256>>>(x, mods, /*sh_mlp*/3 * DD, /*sc_mlp*/4 * DD, hx);
        gemm<3, true>(hx, DD, 0, wf1 + (size_t)i * DFF_ * DD, DD, 0,
                      h1, DFF_, 0, nullptr, 0, f1b + (size_t)i * DFF_, nullptr, LL, DFF_, DD, 1);
        gemm<2, true>(h1, DFF_, 0, wf2 + (size_t)i * DD * DFF_, DFF_, 0,
                      x, DD, 0, x, 0, f2b + (size_t)i * DD, mods + 5 * DD, LL, DD, DFF_, 1);
    }
}